// round 8
// baseline (speedup 1.0000x reference)
#include <cuda_runtime.h>
#include <math.h>

#define Bb 2
#define Hh 48
#define Ww 48
#define Cc 256
#define NHh 8
#define HDd 32
#define Ll 2304          // 48*48
#define Rr (Bb*Ll)       // 4608
#define SCALING 0.17677669529663687f  // 32^-0.5

// scratch (no cudaMalloc allowed)
__device__ float g_q[Rr*Cc];
__device__ float g_k[Rr*Cc];
__device__ float g_v[Rr*Cc];
__device__ float g_attn[Rr*Cc];
__device__ float g_lepe[Rr*Cc];

// ---------------------------------------------------------------------------
// helpers
// ---------------------------------------------------------------------------
__device__ __forceinline__ unsigned f2tf(float x) {
    unsigned u;
    asm("cvt.rna.tf32.f32 %0, %1;" : "=r"(u) : "f"(x));
    return u;
}
__device__ __forceinline__ float f2tff(float x) {
    return __uint_as_float(f2tf(x));
}

__device__ __forceinline__ void mma8(float4& c,
                                     unsigned a0, unsigned a1, unsigned a2, unsigned a3,
                                     unsigned b0, unsigned b1) {
    asm volatile(
        "mma.sync.aligned.m16n8k8.row.col.f32.tf32.tf32.f32 "
        "{%0,%1,%2,%3},{%4,%5,%6,%7},{%8,%9},{%0,%1,%2,%3};\n"
        : "+f"(c.x), "+f"(c.y), "+f"(c.z), "+f"(c.w)
        : "r"(a0), "r"(a1), "r"(a2), "r"(a3), "r"(b0), "r"(b1));
}

__device__ __forceinline__ void cpa16(void* dst, const void* src) {
    unsigned d = (unsigned)__cvta_generic_to_shared(dst);
    asm volatile("cp.async.ca.shared.global [%0], [%1], 16;\n" :: "r"(d), "l"(src));
}
#define CP_COMMIT() asm volatile("cp.async.commit_group;\n" ::: "memory")
#define CP_WAIT1()  asm volatile("cp.async.wait_group 1;\n" ::: "memory")
#define CP_WAIT2()  asm volatile("cp.async.wait_group 2;\n" ::: "memory")

__device__ __forceinline__ void cvt_inplace4(float* p) {
    float4 v = *reinterpret_cast<float4*>(p);
    v.x = f2tff(v.x); v.y = f2tff(v.y); v.z = f2tff(v.z); v.w = f2tff(v.w);
    *reinterpret_cast<float4*>(p) = v;
}

// ---------------------------------------------------------------------------
// Fused QKV tf32 GEMM, cp.async double-buffered.
// 64x64 block, BK=32, 4 warps (2x2 of 32x32 warp tiles), m16n8k8.
// dynamic smem: As[2][64][36] | Bs[2][3][32][72]
// ---------------------------------------------------------------------------
#define QKV_AS 0
#define QKV_BS (2*64*36)
#define QKV_SMEM (QKV_BS + 2*3*32*72)

__global__ __launch_bounds__(128) void qkv_tc_kernel(
    const float* __restrict__ x,
    const float* __restrict__ wq, const float* __restrict__ bq,
    const float* __restrict__ wk, const float* __restrict__ bk,
    const float* __restrict__ wv, const float* __restrict__ bv,
    const float* __restrict__ sinp, const float* __restrict__ cosp)
{
    extern __shared__ float sm[];
    float (*As)[64][36]    = reinterpret_cast<float(*)[64][36]>(sm + QKV_AS);
    float (*Bs)[3][32][72] = reinterpret_cast<float(*)[3][32][72]>(sm + QKV_BS);

    int tid = threadIdx.x;
    int warp = tid >> 5, lane = tid & 31;
    int g = lane >> 2, t = lane & 3;
    int wm = warp >> 1, wn = warp & 1;
    int row0 = blockIdx.x * 64;
    int col0 = blockIdx.y * 64;

    const float* Wm[3] = { wq, wk, wv };

    // staging coords
    int ar = tid >> 1, ac = (tid & 1) * 16;        // A: row 0..63, col base
    int br = tid >> 2, bc = (tid & 3) * 16;        // B: row 0..31, col base

    // prologue: stage k-iter 0 into buf 0
    #pragma unroll
    for (int j = 0; j < 4; ++j)
        cpa16(&As[0][ar][ac + j*4], &x[(size_t)(row0+ar)*Cc + ac + j*4]);
    #pragma unroll
    for (int m = 0; m < 3; ++m)
        #pragma unroll
        for (int j = 0; j < 4; ++j)
            cpa16(&Bs[0][m][br][bc + j*4], &Wm[m][(size_t)br*Cc + col0 + bc + j*4]);
    CP_COMMIT();

    float4 c[3][2][4];
    #pragma unroll
    for (int m = 0; m < 3; ++m)
        #pragma unroll
        for (int i = 0; i < 2; ++i)
            #pragma unroll
            for (int j = 0; j < 4; ++j) c[m][i][j] = make_float4(0.f,0.f,0.f,0.f);

    for (int it = 0; it < 8; ++it) {
        int buf = it & 1;
        int ktn = (it + 1) * 32;
        if (ktn < Cc) {
            int ob = buf ^ 1;
            #pragma unroll
            for (int j = 0; j < 4; ++j)
                cpa16(&As[ob][ar][ac + j*4], &x[(size_t)(row0+ar)*Cc + ktn + ac + j*4]);
            #pragma unroll
            for (int m = 0; m < 3; ++m)
                #pragma unroll
                for (int j = 0; j < 4; ++j)
                    cpa16(&Bs[ob][m][br][bc + j*4], &Wm[m][(size_t)(ktn+br)*Cc + col0 + bc + j*4]);
        }
        CP_COMMIT();
        CP_WAIT1();
        // in-place RNA cvt of own staged regions (current buf)
        #pragma unroll
        for (int j = 0; j < 4; ++j) cvt_inplace4(&As[buf][ar][ac + j*4]);
        #pragma unroll
        for (int m = 0; m < 3; ++m)
            #pragma unroll
            for (int j = 0; j < 4; ++j) cvt_inplace4(&Bs[buf][m][br][bc + j*4]);
        __syncthreads();

        #pragma unroll
        for (int kc = 0; kc < 4; ++kc) {
            unsigned a[2][4];
            #pragma unroll
            for (int i = 0; i < 2; ++i) {
                int rbase = wm*32 + i*16;
                a[i][0] = __float_as_uint(As[buf][rbase+g  ][kc*8+t  ]);
                a[i][1] = __float_as_uint(As[buf][rbase+g+8][kc*8+t  ]);
                a[i][2] = __float_as_uint(As[buf][rbase+g  ][kc*8+t+4]);
                a[i][3] = __float_as_uint(As[buf][rbase+g+8][kc*8+t+4]);
            }
            #pragma unroll
            for (int j = 0; j < 4; ++j) {
                #pragma unroll
                for (int m = 0; m < 3; ++m) {
                    unsigned b0 = __float_as_uint(Bs[buf][m][kc*8+t  ][wn*32 + j*8 + g]);
                    unsigned b1 = __float_as_uint(Bs[buf][m][kc*8+t+4][wn*32 + j*8 + g]);
                    #pragma unroll
                    for (int i = 0; i < 2; ++i)
                        mma8(c[m][i][j], a[i][0], a[i][1], a[i][2], a[i][3], b0, b1);
                }
            }
        }
        __syncthreads();
    }

    // epilogue: q (rope), k (scale+rope), v (plain)
    #pragma unroll
    for (int j = 0; j < 4; ++j) {
        int cb = col0 + wn*32 + j*8 + 2*t;
        int hd = cb & 31;
        float2 biq = *reinterpret_cast<const float2*>(&bq[cb]);
        float2 bik = *reinterpret_cast<const float2*>(&bk[cb]);
        float2 biv = *reinterpret_cast<const float2*>(&bv[cb]);
        #pragma unroll
        for (int i = 0; i < 2; ++i) {
            int r0 = row0 + wm*32 + i*16 + g;
            int r1 = r0 + 8;
            int l0 = (r0 >= Ll) ? r0 - Ll : r0;
            int l1 = (r1 >= Ll) ? r1 - Ll : r1;
            float2 s0 = *reinterpret_cast<const float2*>(&sinp[(size_t)l0*HDd + hd]);
            float2 c0 = *reinterpret_cast<const float2*>(&cosp[(size_t)l0*HDd + hd]);
            float2 s1 = *reinterpret_cast<const float2*>(&sinp[(size_t)l1*HDd + hd]);
            float2 c1 = *reinterpret_cast<const float2*>(&cosp[(size_t)l1*HDd + hd]);
            {
                float v0 = c[0][i][j].x + biq.x, v1 = c[0][i][j].y + biq.y;
                float w0 = c[0][i][j].z + biq.x, w1 = c[0][i][j].w + biq.y;
                float e0 = v0*c0.x - v1*s0.x, o0 = v1*c0.y + v0*s0.y;
                float e1 = w0*c1.x - w1*s1.x, o1 = w1*c1.y + w0*s1.y;
                *reinterpret_cast<float2*>(&g_q[(size_t)r0*Cc + cb]) = make_float2(e0, o0);
                *reinterpret_cast<float2*>(&g_q[(size_t)r1*Cc + cb]) = make_float2(e1, o1);
            }
            {
                float v0 = (c[1][i][j].x + bik.x)*SCALING, v1 = (c[1][i][j].y + bik.y)*SCALING;
                float w0 = (c[1][i][j].z + bik.x)*SCALING, w1 = (c[1][i][j].w + bik.y)*SCALING;
                float e0 = v0*c0.x - v1*s0.x, o0 = v1*c0.y + v0*s0.y;
                float e1 = w0*c1.x - w1*s1.x, o1 = w1*c1.y + w0*s1.y;
                *reinterpret_cast<float2*>(&g_k[(size_t)r0*Cc + cb]) = make_float2(e0, o0);
                *reinterpret_cast<float2*>(&g_k[(size_t)r1*Cc + cb]) = make_float2(e1, o1);
            }
            {
                float v0 = c[2][i][j].x + biv.x, v1 = c[2][i][j].y + biv.y;
                float w0 = c[2][i][j].z + biv.x, w1 = c[2][i][j].w + biv.y;
                *reinterpret_cast<float2*>(&g_v[(size_t)r0*Cc + cb]) = make_float2(v0, v1);
                *reinterpret_cast<float2*>(&g_v[(size_t)r1*Cc + cb]) = make_float2(w0, w1);
            }
        }
    }
}

// ---------------------------------------------------------------------------
// Out-projection: out = (attn + lepe) @ W + bias, cp.async double-buffered.
// dynamic smem: As[2][64][36] | A2s[2][64][36] | Bs[2][32][72]
// ---------------------------------------------------------------------------
#define OP_AS  0
#define OP_A2S (2*64*36)
#define OP_BS  (OP_A2S + 2*64*36)
#define OP_SMEM (OP_BS + 2*32*72)

__global__ __launch_bounds__(128) void gemm_tc_kernel(
    const float* __restrict__ A, const float* __restrict__ A2,
    const float* __restrict__ W, const float* __restrict__ bias,
    float* __restrict__ out)
{
    extern __shared__ float sm[];
    float (*As)[64][36]  = reinterpret_cast<float(*)[64][36]>(sm + OP_AS);
    float (*A2s)[64][36] = reinterpret_cast<float(*)[64][36]>(sm + OP_A2S);
    float (*Bs)[32][72]  = reinterpret_cast<float(*)[32][72]>(sm + OP_BS);

    int tid = threadIdx.x;
    int warp = tid >> 5, lane = tid & 31;
    int g = lane >> 2, t = lane & 3;
    int wm = warp >> 1, wn = warp & 1;
    int row0 = blockIdx.x * 64;
    int col0 = blockIdx.y * 64;

    int ar = tid >> 1, ac = (tid & 1) * 16;
    int br = tid >> 2, bc = (tid & 3) * 16;

    #pragma unroll
    for (int j = 0; j < 4; ++j) {
        cpa16(&As[0][ar][ac + j*4],  &A [(size_t)(row0+ar)*Cc + ac + j*4]);
        cpa16(&A2s[0][ar][ac + j*4], &A2[(size_t)(row0+ar)*Cc + ac + j*4]);
        cpa16(&Bs[0][br][bc + j*4],  &W [(size_t)br*Cc + col0 + bc + j*4]);
    }
    CP_COMMIT();

    float4 c[2][4];
    #pragma unroll
    for (int i = 0; i < 2; ++i)
        #pragma unroll
        for (int j = 0; j < 4; ++j) c[i][j] = make_float4(0.f,0.f,0.f,0.f);

    for (int it = 0; it < 8; ++it) {
        int buf = it & 1;
        int ktn = (it + 1) * 32;
        if (ktn < Cc) {
            int ob = buf ^ 1;
            #pragma unroll
            for (int j = 0; j < 4; ++j) {
                cpa16(&As[ob][ar][ac + j*4],  &A [(size_t)(row0+ar)*Cc + ktn + ac + j*4]);
                cpa16(&A2s[ob][ar][ac + j*4], &A2[(size_t)(row0+ar)*Cc + ktn + ac + j*4]);
                cpa16(&Bs[ob][br][bc + j*4],  &W [(size_t)(ktn+br)*Cc + col0 + bc + j*4]);
            }
        }
        CP_COMMIT();
        CP_WAIT1();
        // combine A + A2 (fp32 add then RNA cvt), cvt B
        #pragma unroll
        for (int j = 0; j < 4; ++j) {
            float4 v  = *reinterpret_cast<float4*>(&As[buf][ar][ac + j*4]);
            float4 v2 = *reinterpret_cast<float4*>(&A2s[buf][ar][ac + j*4]);
            v.x = f2tff(v.x + v2.x); v.y = f2tff(v.y + v2.y);
            v.z = f2tff(v.z + v2.z); v.w = f2tff(v.w + v2.w);
            *reinterpret_cast<float4*>(&As[buf][ar][ac + j*4]) = v;
            cvt_inplace4(&Bs[buf][br][bc + j*4]);
        }
        __syncthreads();

        #pragma unroll
        for (int kc = 0; kc < 4; ++kc) {
            unsigned a[2][4];
            #pragma unroll
            for (int i = 0; i < 2; ++i) {
                int rbase = wm*32 + i*16;
                a[i][0] = __float_as_uint(As[buf][rbase+g  ][kc*8+t  ]);
                a[i][1] = __float_as_uint(As[buf][rbase+g+8][kc*8+t  ]);
                a[i][2] = __float_as_uint(As[buf][rbase+g  ][kc*8+t+4]);
                a[i][3] = __float_as_uint(As[buf][rbase+g+8][kc*8+t+4]);
            }
            #pragma unroll
            for (int j = 0; j < 4; ++j) {
                unsigned b0 = __float_as_uint(Bs[buf][kc*8+t  ][wn*32 + j*8 + g]);
                unsigned b1 = __float_as_uint(Bs[buf][kc*8+t+4][wn*32 + j*8 + g]);
                #pragma unroll
                for (int i = 0; i < 2; ++i)
                    mma8(c[i][j], a[i][0], a[i][1], a[i][2], a[i][3], b0, b1);
            }
        }
        __syncthreads();
    }

    #pragma unroll
    for (int j = 0; j < 4; ++j) {
        int cb = col0 + wn*32 + j*8 + 2*t;
        float2 bi = *reinterpret_cast<const float2*>(&bias[cb]);
        #pragma unroll
        for (int i = 0; i < 2; ++i) {
            int r0 = row0 + wm*32 + i*16 + g;
            int r1 = r0 + 8;
            *reinterpret_cast<float2*>(&out[(size_t)r0*Cc + cb]) =
                make_float2(c[i][j].x + bi.x, c[i][j].y + bi.y);
            *reinterpret_cast<float2*>(&out[(size_t)r1*Cc + cb]) =
                make_float2(c[i][j].z + bi.x, c[i][j].w + bi.y);
        }
    }
}

// ---------------------------------------------------------------------------
// Depthwise 5x5 conv (LEPE): float4/thread, branchless interior fast path.
// ---------------------------------------------------------------------------
__global__ __launch_bounds__(256) void lepe_kernel(
    const float* __restrict__ wdw, const float* __restrict__ bdw)
{
    int tid = threadIdx.x;
    int c4 = (tid & 63) * 4;
    int l = blockIdx.x * 4 + (tid >> 6);
    int b = blockIdx.y;
    int h = l / Ww;
    int w = l - h*Ww;

    float4 acc = *reinterpret_cast<const float4*>(&bdw[c4]);
    const float* vb = g_v + (size_t)b*Ll*Cc;

    if (h >= 2 && h <= Hh-3 && w >= 2 && w <= Ww-3) {
        #pragma unroll
        for (int kh = 0; kh < 5; ++kh) {
            #pragma unroll
            for (int kw = 0; kw < 5; ++kw) {
                float4 vv = *reinterpret_cast<const float4*>(
                    &vb[((size_t)(h+kh-2)*Ww + (w+kw-2))*Cc + c4]);
                float4 wt = *reinterpret_cast<const float4*>(&wdw[(kh*5+kw)*Cc + c4]);
                acc.x = fmaf(vv.x, wt.x, acc.x);
                acc.y = fmaf(vv.y, wt.y, acc.y);
                acc.z = fmaf(vv.z, wt.z, acc.z);
                acc.w = fmaf(vv.w, wt.w, acc.w);
            }
        }
    } else {
        #pragma unroll
        for (int kh = 0; kh < 5; ++kh) {
            int hh = h + kh - 2;
            if ((unsigned)hh >= (unsigned)Hh) continue;
            #pragma unroll
            for (int kw = 0; kw < 5; ++kw) {
                int ww2 = w + kw - 2;
                if ((unsigned)ww2 >= (unsigned)Ww) continue;
                float4 vv = *reinterpret_cast<const float4*>(
                    &vb[((size_t)hh*Ww + ww2)*Cc + c4]);
                float4 wt = *reinterpret_cast<const float4*>(&wdw[(kh*5+kw)*Cc + c4]);
                acc.x = fmaf(vv.x, wt.x, acc.x);
                acc.y = fmaf(vv.y, wt.y, acc.y);
                acc.z = fmaf(vv.z, wt.z, acc.z);
                acc.w = fmaf(vv.w, wt.w, acc.w);
            }
        }
    }
    *reinterpret_cast<float4*>(&g_lepe[((size_t)b*Ll + l)*Cc + c4]) = acc;
}

// ---------------------------------------------------------------------------
// Flash attention: 4 warps x 32 Q-rows (two 16-row A-sets share B-frags).
// cp.async pipelines K/V (double-buffered) + mask tile.
// dynamic smem: Ks[2][64][36] | Vs[2][64][40] | Ps[4][32][68] | Ms[128][72]
// ---------------------------------------------------------------------------
#define KS_OFF 0
#define VS_OFF (2*64*36)
#define PS_OFF (VS_OFF + 2*64*40)
#define MS_OFF (PS_OFF + 4*32*68)
#define ATT_SMEM (MS_OFF + 128*72)

__global__ __launch_bounds__(128) void attn_tc_kernel(const float* __restrict__ mask)
{
    extern __shared__ float sm[];
    float (*Ks)[64][36] = reinterpret_cast<float(*)[64][36]>(sm + KS_OFF);
    float (*Vs)[64][40] = reinterpret_cast<float(*)[64][40]>(sm + VS_OFF);
    float (*Ps)[32][68] = reinterpret_cast<float(*)[32][68]>(sm + PS_OFF);
    float (*Ms)[72]     = reinterpret_cast<float(*)[72]>(sm + MS_OFF);

    int tid  = threadIdx.x;
    int warp = tid >> 5, lane = tid & 31;
    int g = lane >> 2, t = lane & 3;
    int n = blockIdx.y >> 1, b = blockIdx.y & 1;
    int l0 = blockIdx.x * 128;
    int qrow = l0 + warp*32;

    const float* qb = g_q + ((size_t)(b*Ll + qrow))*Cc + n*HDd;
    const float* kb = g_k + ((size_t)b*Ll)*Cc + n*HDd;
    const float* vb = g_v + ((size_t)b*Ll)*Cc + n*HDd;
    const float* mbb = mask + ((size_t)n*Ll + l0)*Ll;

    // persistent Q fragments: 2 sets of 16 rows
    unsigned qa[2][4][4];
    #pragma unroll
    for (int i = 0; i < 2; ++i)
        #pragma unroll
        for (int kc = 0; kc < 4; ++kc) {
            qa[i][kc][0] = f2tf(qb[(size_t)(i*16+g  )*Cc + kc*8 + t]);
            qa[i][kc][1] = f2tf(qb[(size_t)(i*16+g+8)*Cc + kc*8 + t]);
            qa[i][kc][2] = f2tf(qb[(size_t)(i*16+g  )*Cc + kc*8 + t + 4]);
            qa[i][kc][3] = f2tf(qb[(size_t)(i*16+g+8)*Cc + kc*8 + t + 4]);
        }

    // K/V staging: r = tid>>1 (0..63), 16-float half per thread
    int sr = tid >> 1;
    int scb = (tid & 1) * 16;

    #pragma unroll
    for (int j = 0; j < 4; ++j) {
        cpa16(&Ks[0][sr][scb + j*4], &kb[(size_t)sr*Cc + scb + j*4]);
        cpa16(&Vs[0][sr][scb + j*4], &vb[(size_t)sr*Cc + scb + j*4]);
    }
    CP_COMMIT();

    float mm[2][2], ll[2][2];
    #pragma unroll
    for (int i = 0; i < 2; ++i) { mm[i][0]=mm[i][1]=-1e30f; ll[i][0]=ll[i][1]=0.f; }
    float4 o[2][4] = {};

    for (int tile = 0; tile < Ll/64; ++tile) {
        int buf = tile & 1;
        int m0 = tile * 64;

        // stage mask tile: 16 cpa16/thread (128 rows x 64 cols)
        #pragma unroll
        for (int kk = 0; kk < 16; ++kk) {
            int oidx = tid + kk*128;
            int mr = oidx >> 4, seg = (oidx & 15) * 4;
            cpa16(&Ms[mr][seg], &mbb[(size_t)mr*Ll + m0 + seg]);
        }
        CP_COMMIT();

        if (m0 + 64 < Ll) {
            int nb0 = m0 + 64, ob = buf ^ 1;
            #pragma unroll
            for (int j = 0; j < 4; ++j) {
                cpa16(&Ks[ob][sr][scb + j*4], &kb[(size_t)(nb0+sr)*Cc + scb + j*4]);
                cpa16(&Vs[ob][sr][scb + j*4], &vb[(size_t)(nb0+sr)*Cc + scb + j*4]);
            }
        }
        CP_COMMIT();

        CP_WAIT2();   // KV_i complete
        #pragma unroll
        for (int j = 0; j < 4; ++j) {
            cvt_inplace4(&Ks[buf][sr][scb + j*4]);
            cvt_inplace4(&Vs[buf][sr][scb + j*4]);
        }
        __syncthreads();

        // S = Q @ K^T : 32x64 per warp, B-frags shared across both A-sets
        float4 s[2][8];
        #pragma unroll
        for (int i = 0; i < 2; ++i)
            #pragma unroll
            for (int nb = 0; nb < 8; ++nb) s[i][nb] = make_float4(0.f,0.f,0.f,0.f);
        #pragma unroll
        for (int nb = 0; nb < 8; ++nb) {
            #pragma unroll
            for (int kc = 0; kc < 4; ++kc) {
                unsigned b0 = __float_as_uint(Ks[buf][nb*8+g][kc*8+t]);
                unsigned b1 = __float_as_uint(Ks[buf][nb*8+g][kc*8+t+4]);
                mma8(s[0][nb], qa[0][kc][0], qa[0][kc][1], qa[0][kc][2], qa[0][kc][3], b0, b1);
                mma8(s[1][nb], qa[1][kc][0], qa[1][kc][1], qa[1][kc][2], qa[1][kc][3], b0, b1);
            }
        }

        CP_WAIT1();       // mask tile complete
        __syncthreads();

        // + mask, online softmax per set
        float sc[2][2];
        #pragma unroll
        for (int i = 0; i < 2; ++i) {
            int mrA = warp*32 + i*16 + g, mrB = mrA + 8;
            float mxA = -1e30f, mxB = -1e30f;
            #pragma unroll
            for (int nb = 0; nb < 8; ++nb) {
                float2 ma = *reinterpret_cast<const float2*>(&Ms[mrA][nb*8 + 2*t]);
                float2 mc = *reinterpret_cast<const float2*>(&Ms[mrB][nb*8 + 2*t]);
                s[i][nb].x += ma.x; s[i][nb].y += ma.y;
                s[i][nb].z += mc.x; s[i][nb].w += mc.y;
                mxA = fmaxf(mxA, fmaxf(s[i][nb].x, s[i][nb].y));
                mxB = fmaxf(mxB, fmaxf(s[i][nb].z, s[i][nb].w));
            }
            mxA = fmaxf(mxA, __shfl_xor_sync(0xffffffffu, mxA, 1));
            mxA = fmaxf(mxA, __shfl_xor_sync(0xffffffffu, mxA, 2));
            mxB = fmaxf(mxB, __shfl_xor_sync(0xffffffffu, mxB, 1));
            mxB = fmaxf(mxB, __shfl_xor_sync(0xffffffffu, mxB, 2));
            float mAn = fmaxf(mm[i][0], mxA), mBn = fmaxf(mm[i][1], mxB);
            sc[i][0] = __expf(mm[i][0] - mAn);
            sc[i][1] = __expf(mm[i][1] - mBn);
            mm[i][0] = mAn; mm[i][1] = mBn;

            float sA = 0.f, sB = 0.f;
            #pragma unroll
            for (int nb = 0; nb < 8; ++nb) {
                float p0 = __expf(s[i][nb].x - mAn);
                float p1 = __expf(s[i][nb].y - mAn);
                float p2 = __expf(s[i][nb].z - mBn);
                float p3 = __expf(s[i][nb].w - mBn);
                sA += p0 + p1; sB += p2 + p3;
                Ps[warp][i*16+g  ][nb*8 + 2*t    ] = __uint_as_float(f2tf(p0));
                Ps[warp][i*16+g  ][nb*8 + 2*t + 1] = __uint_as_float(f2tf(p1));
                Ps[warp][i*16+g+8][nb*8 + 2*t    ] = __uint_as_float(f2tf(p2));
                Ps[warp][i*16+g+8][nb*8 + 2*t + 1] = __uint_as_float(f2tf(p3));
            }
            sA += __shfl_xor_sync(0xffffffffu, sA, 1);
            sA += __shfl_xor_sync(0xffffffffu, sA, 2);
            sB += __shfl_xor_sync(0xffffffffu, sB, 1);
            sB += __shfl_xor_sync(0xffffffffu, sB, 2);
            ll[i][0] = ll[i][0]*sc[i][0] + sA;
            ll[i][1] = ll[i][1]*sc[i][1] + sB;

            #pragma unroll
            for (int nv = 0; nv < 4; ++nv) {
                o[i][nv].x *= sc[i][0]; o[i][nv].y *= sc[i][0];
                o[i][nv].z *= sc[i][1]; o[i][nv].w *= sc[i][1];
            }
        }
        __syncwarp();

        // O += P @ V (B-frags shared across sets)
        #pragma unroll
        for (int kc = 0; kc < 8; ++kc) {
            unsigned a[2][4];
            #pragma unroll
            for (int i = 0; i < 2; ++i) {
                a[i][0] = __float_as_uint(Ps[warp][i*16+g  ][kc*8 + t    ]);
                a[i][1] = __float_as_uint(Ps[warp][i*16+g+8][kc*8 + t    ]);
                a[i][2] = __float_as_uint(Ps[warp][i*16+g  ][kc*8 + t + 4]);
                a[i][3] = __float_as_uint(Ps[warp][i*16+g+8][kc*8 + t + 4]);
            }
            #pragma unroll
            for (int nv = 0; nv < 4; ++nv) {
                unsigned b0 = __float_as_uint(Vs[buf][kc*8 + t    ][nv*8 + g]);
                unsigned b1 = __float_as_uint(Vs[buf][kc*8 + t + 4][nv*8 + g]);
                mma8(o[0][nv], a[0][0], a[0][1], a[0][2], a[0][3], b0, b1);
                mma8(o[1][nv], a[1][0], a[1][1], a[1][2], a[1][3], b0, b1);
            }
        }
        __syncthreads();
    }

    #pragma unroll
    for (int i = 0; i < 2; ++i) {
        float invA = 1.f / ll[i][0], invB = 1.f / ll[i][1];
        float* ob = g_attn + ((size_t)(b*Ll + qrow + i*16))*Cc + n*HDd;
        #pragma unroll
        for (int nv = 0; nv < 4; ++nv) {
            *reinterpret_cast<float2*>(&ob[(size_t)g*Cc + nv*8 + 2*t]) =
                make_float2(o[i][nv].x*invA, o[i][nv].y*invA);
            *reinterpret_cast<float2*>(&ob[(size_t)(g+8)*Cc + nv*8 + 2*t]) =
                make_float2(o[i][nv].z*invB, o[i][nv].w*invB);
        }
    }
}

// ---------------------------------------------------------------------------
extern "C" void kernel_launch(void* const* d_in, const int* in_sizes, int n_in,
                              void* d_out, int out_size)
{
    const float* x    = (const float*)d_in[0];
    const float* sinp = (const float*)d_in[1];
    const float* cosp = (const float*)d_in[2];
    const float* mask = (const float*)d_in[3];
    const float* wq   = (const float*)d_in[4];
    const float* bq   = (const float*)d_in[5];
    const float* wk   = (const float*)d_in[6];
    const float* bk   = (const float*)d_in[7];
    const float* wv   = (const float*)d_in[8];
    const float* bv   = (const float*)d_in[9];
    const float* wdw  = (const float*)d_in[10];
    const float* bdw  = (const float*)d_in[11];
    const float* wo   = (const float*)d_in[12];
    const float* bo   = (const float*)d_in[13];

    float *pa, *pl;
    cudaGetSymbolAddress((void**)&pa, g_attn);
    cudaGetSymbolAddress((void**)&pl, g_lepe);

    cudaFuncSetAttribute(attn_tc_kernel, cudaFuncAttributeMaxDynamicSharedMemorySize,
                         ATT_SMEM * (int)sizeof(float));
    cudaFuncSetAttribute(qkv_tc_kernel, cudaFuncAttributeMaxDynamicSharedMemorySize,
                         QKV_SMEM * (int)sizeof(float));
    cudaFuncSetAttribute(gemm_tc_kernel, cudaFuncAttributeMaxDynamicSharedMemorySize,
                         OP_SMEM * (int)sizeof(float));

    dim3 gg(Rr/64, Cc/64);
    qkv_tc_kernel<<<gg, 128, QKV_SMEM*sizeof(float)>>>(x, wq, bq, wk, bk, wv, bv, sinp, cosp);

    lepe_kernel<<<dim3(Ll/4, Bb), 256>>>(wdw, bdw);

    attn_tc_kernel<<<dim3(Ll/128, Bb*NHh), 128, ATT_SMEM*sizeof(float)>>>(mask);

    gemm_tc_kernel<<<gg, 128, OP_SMEM*sizeof(float)>>>(pa, pl, wo, bo, (float*)d_out);
}

// round 10
// speedup vs baseline: 1.0969x; 1.0969x over previous
#include <cuda_runtime.h>
#include <math.h>

#define Bb 2
#define Hh 48
#define Ww 48
#define Cc 256
#define NHh 8
#define HDd 32
#define Ll 2304          // 48*48
#define Rr (Bb*Ll)       // 4608
#define SCALING 0.17677669529663687f  // 32^-0.5

// scratch (no cudaMalloc allowed)
__device__ float g_q[Rr*Cc];
__device__ float g_k[Rr*Cc];
__device__ float g_v[Rr*Cc];
__device__ float g_attn[Rr*Cc];
__device__ float g_lepe[Rr*Cc];

// ---------------------------------------------------------------------------
// helpers
// ---------------------------------------------------------------------------
__device__ __forceinline__ unsigned f2tf(float x) {
    unsigned u;
    asm("cvt.rna.tf32.f32 %0, %1;" : "=r"(u) : "f"(x));
    return u;
}
__device__ __forceinline__ float f2tff(float x) {
    return __uint_as_float(f2tf(x));
}

__device__ __forceinline__ void mma8(float4& c,
                                     unsigned a0, unsigned a1, unsigned a2, unsigned a3,
                                     unsigned b0, unsigned b1) {
    asm volatile(
        "mma.sync.aligned.m16n8k8.row.col.f32.tf32.tf32.f32 "
        "{%0,%1,%2,%3},{%4,%5,%6,%7},{%8,%9},{%0,%1,%2,%3};\n"
        : "+f"(c.x), "+f"(c.y), "+f"(c.z), "+f"(c.w)
        : "r"(a0), "r"(a1), "r"(a2), "r"(a3), "r"(b0), "r"(b1));
}

__device__ __forceinline__ void cpa16(void* dst, const void* src) {
    unsigned d = (unsigned)__cvta_generic_to_shared(dst);
    asm volatile("cp.async.ca.shared.global [%0], [%1], 16;\n" :: "r"(d), "l"(src));
}
#define CP_COMMIT() asm volatile("cp.async.commit_group;\n" ::: "memory")
#define CP_WAIT1()  asm volatile("cp.async.wait_group 1;\n" ::: "memory")
#define CP_WAIT2()  asm volatile("cp.async.wait_group 2;\n" ::: "memory")

__device__ __forceinline__ void cvt_inplace4(float* p) {
    float4 v = *reinterpret_cast<float4*>(p);
    v.x = f2tff(v.x); v.y = f2tff(v.y); v.z = f2tff(v.z); v.w = f2tff(v.w);
    *reinterpret_cast<float4*>(p) = v;
}

// ---------------------------------------------------------------------------
// Fused QKV tf32 GEMM: BM=128, BN=64, BK=32; 256 threads (8 warps, 4x2),
// each warp 32x32 (two 16-row A-sets sharing B-frags); cp.async double-buffered.
// dynamic smem: As[2][128][36] | Bs[2][3][32][72]
// ---------------------------------------------------------------------------
#define QKV_AS 0
#define QKV_BS (2*128*36)
#define QKV_SMEM (QKV_BS + 2*3*32*72)

__global__ __launch_bounds__(256) void qkv_tc_kernel(
    const float* __restrict__ x,
    const float* __restrict__ wq, const float* __restrict__ bq,
    const float* __restrict__ wk, const float* __restrict__ bk,
    const float* __restrict__ wv, const float* __restrict__ bv,
    const float* __restrict__ sinp, const float* __restrict__ cosp)
{
    extern __shared__ float sm[];
    float (*As)[128][36]   = reinterpret_cast<float(*)[128][36]>(sm + QKV_AS);
    float (*Bs)[3][32][72] = reinterpret_cast<float(*)[3][32][72]>(sm + QKV_BS);

    int tid = threadIdx.x;
    int warp = tid >> 5, lane = tid & 31;
    int g = lane >> 2, t = lane & 3;
    int wm = warp >> 1, wn = warp & 1;   // wm 0..3, wn 0..1
    int row0 = blockIdx.x * 128;
    int col0 = blockIdx.y * 64;

    const float* Wm[3] = { wq, wk, wv };

    // staging coords
    int ar = tid >> 1, ac = (tid & 1) * 16;   // A: 128 rows, 4 cpa16/thread
    int br = tid >> 3, bc = (tid & 7) * 8;    // B: 32 rows, 2 cpa16/thread per m

    #pragma unroll
    for (int j = 0; j < 4; ++j)
        cpa16(&As[0][ar][ac + j*4], &x[(size_t)(row0+ar)*Cc + ac + j*4]);
    #pragma unroll
    for (int m = 0; m < 3; ++m)
        #pragma unroll
        for (int j = 0; j < 2; ++j)
            cpa16(&Bs[0][m][br][bc + j*4], &Wm[m][(size_t)br*Cc + col0 + bc + j*4]);
    CP_COMMIT();

    float4 c[3][2][4];
    #pragma unroll
    for (int m = 0; m < 3; ++m)
        #pragma unroll
        for (int i = 0; i < 2; ++i)
            #pragma unroll
            for (int j = 0; j < 4; ++j) c[m][i][j] = make_float4(0.f,0.f,0.f,0.f);

    for (int it = 0; it < 8; ++it) {
        int buf = it & 1;
        int ktn = (it + 1) * 32;
        if (ktn < Cc) {
            int ob = buf ^ 1;
            #pragma unroll
            for (int j = 0; j < 4; ++j)
                cpa16(&As[ob][ar][ac + j*4], &x[(size_t)(row0+ar)*Cc + ktn + ac + j*4]);
            #pragma unroll
            for (int m = 0; m < 3; ++m)
                #pragma unroll
                for (int j = 0; j < 2; ++j)
                    cpa16(&Bs[ob][m][br][bc + j*4], &Wm[m][(size_t)(ktn+br)*Cc + col0 + bc + j*4]);
        }
        CP_COMMIT();
        CP_WAIT1();
        #pragma unroll
        for (int j = 0; j < 4; ++j) cvt_inplace4(&As[buf][ar][ac + j*4]);
        #pragma unroll
        for (int m = 0; m < 3; ++m)
            #pragma unroll
            for (int j = 0; j < 2; ++j) cvt_inplace4(&Bs[buf][m][br][bc + j*4]);
        __syncthreads();

        #pragma unroll
        for (int kc = 0; kc < 4; ++kc) {
            unsigned a[2][4];
            #pragma unroll
            for (int i = 0; i < 2; ++i) {
                int rbase = wm*32 + i*16;
                a[i][0] = __float_as_uint(As[buf][rbase+g  ][kc*8+t  ]);
                a[i][1] = __float_as_uint(As[buf][rbase+g+8][kc*8+t  ]);
                a[i][2] = __float_as_uint(As[buf][rbase+g  ][kc*8+t+4]);
                a[i][3] = __float_as_uint(As[buf][rbase+g+8][kc*8+t+4]);
            }
            #pragma unroll
            for (int j = 0; j < 4; ++j) {
                #pragma unroll
                for (int m = 0; m < 3; ++m) {
                    unsigned b0 = __float_as_uint(Bs[buf][m][kc*8+t  ][wn*32 + j*8 + g]);
                    unsigned b1 = __float_as_uint(Bs[buf][m][kc*8+t+4][wn*32 + j*8 + g]);
                    #pragma unroll
                    for (int i = 0; i < 2; ++i)
                        mma8(c[m][i][j], a[i][0], a[i][1], a[i][2], a[i][3], b0, b1);
                }
            }
        }
        __syncthreads();
    }

    // epilogue: q (rope), k (scale+rope), v (plain)
    #pragma unroll
    for (int j = 0; j < 4; ++j) {
        int cb = col0 + wn*32 + j*8 + 2*t;
        int hd = cb & 31;
        float2 biq = *reinterpret_cast<const float2*>(&bq[cb]);
        float2 bik = *reinterpret_cast<const float2*>(&bk[cb]);
        float2 biv = *reinterpret_cast<const float2*>(&bv[cb]);
        #pragma unroll
        for (int i = 0; i < 2; ++i) {
            int r0 = row0 + wm*32 + i*16 + g;
            int r1 = r0 + 8;
            int l0 = (r0 >= Ll) ? r0 - Ll : r0;
            int l1 = (r1 >= Ll) ? r1 - Ll : r1;
            float2 s0 = *reinterpret_cast<const float2*>(&sinp[(size_t)l0*HDd + hd]);
            float2 c0 = *reinterpret_cast<const float2*>(&cosp[(size_t)l0*HDd + hd]);
            float2 s1 = *reinterpret_cast<const float2*>(&sinp[(size_t)l1*HDd + hd]);
            float2 c1 = *reinterpret_cast<const float2*>(&cosp[(size_t)l1*HDd + hd]);
            {
                float v0 = c[0][i][j].x + biq.x, v1 = c[0][i][j].y + biq.y;
                float w0 = c[0][i][j].z + biq.x, w1 = c[0][i][j].w + biq.y;
                float e0 = v0*c0.x - v1*s0.x, o0 = v1*c0.y + v0*s0.y;
                float e1 = w0*c1.x - w1*s1.x, o1 = w1*c1.y + w0*s1.y;
                *reinterpret_cast<float2*>(&g_q[(size_t)r0*Cc + cb]) = make_float2(e0, o0);
                *reinterpret_cast<float2*>(&g_q[(size_t)r1*Cc + cb]) = make_float2(e1, o1);
            }
            {
                float v0 = (c[1][i][j].x + bik.x)*SCALING, v1 = (c[1][i][j].y + bik.y)*SCALING;
                float w0 = (c[1][i][j].z + bik.x)*SCALING, w1 = (c[1][i][j].w + bik.y)*SCALING;
                float e0 = v0*c0.x - v1*s0.x, o0 = v1*c0.y + v0*s0.y;
                float e1 = w0*c1.x - w1*s1.x, o1 = w1*c1.y + w0*s1.y;
                *reinterpret_cast<float2*>(&g_k[(size_t)r0*Cc + cb]) = make_float2(e0, o0);
                *reinterpret_cast<float2*>(&g_k[(size_t)r1*Cc + cb]) = make_float2(e1, o1);
            }
            {
                float v0 = c[2][i][j].x + biv.x, v1 = c[2][i][j].y + biv.y;
                float w0 = c[2][i][j].z + biv.x, w1 = c[2][i][j].w + biv.y;
                *reinterpret_cast<float2*>(&g_v[(size_t)r0*Cc + cb]) = make_float2(v0, v1);
                *reinterpret_cast<float2*>(&g_v[(size_t)r1*Cc + cb]) = make_float2(w0, w1);
            }
        }
    }
}

// ---------------------------------------------------------------------------
// Out-projection: out = (attn + lepe) @ W + bias. BM=128, BN=64, 256 threads.
// dynamic smem: As[2][128][36] | A2s[2][128][36] | Bs[2][32][72]
// ---------------------------------------------------------------------------
#define OP_AS  0
#define OP_A2S (2*128*36)
#define OP_BS  (OP_A2S + 2*128*36)
#define OP_SMEM (OP_BS + 2*32*72)

__global__ __launch_bounds__(256) void gemm_tc_kernel(
    const float* __restrict__ A, const float* __restrict__ A2,
    const float* __restrict__ W, const float* __restrict__ bias,
    float* __restrict__ out)
{
    extern __shared__ float sm[];
    float (*As)[128][36]  = reinterpret_cast<float(*)[128][36]>(sm + OP_AS);
    float (*A2s)[128][36] = reinterpret_cast<float(*)[128][36]>(sm + OP_A2S);
    float (*Bs)[32][72]   = reinterpret_cast<float(*)[32][72]>(sm + OP_BS);

    int tid = threadIdx.x;
    int warp = tid >> 5, lane = tid & 31;
    int g = lane >> 2, t = lane & 3;
    int wm = warp >> 1, wn = warp & 1;
    int row0 = blockIdx.x * 128;
    int col0 = blockIdx.y * 64;

    int ar = tid >> 1, ac = (tid & 1) * 16;
    int br = tid >> 3, bc = (tid & 7) * 8;

    #pragma unroll
    for (int j = 0; j < 4; ++j) {
        cpa16(&As[0][ar][ac + j*4],  &A [(size_t)(row0+ar)*Cc + ac + j*4]);
        cpa16(&A2s[0][ar][ac + j*4], &A2[(size_t)(row0+ar)*Cc + ac + j*4]);
    }
    #pragma unroll
    for (int j = 0; j < 2; ++j)
        cpa16(&Bs[0][br][bc + j*4], &W[(size_t)br*Cc + col0 + bc + j*4]);
    CP_COMMIT();

    float4 c[2][4];
    #pragma unroll
    for (int i = 0; i < 2; ++i)
        #pragma unroll
        for (int j = 0; j < 4; ++j) c[i][j] = make_float4(0.f,0.f,0.f,0.f);

    for (int it = 0; it < 8; ++it) {
        int buf = it & 1;
        int ktn = (it + 1) * 32;
        if (ktn < Cc) {
            int ob = buf ^ 1;
            #pragma unroll
            for (int j = 0; j < 4; ++j) {
                cpa16(&As[ob][ar][ac + j*4],  &A [(size_t)(row0+ar)*Cc + ktn + ac + j*4]);
                cpa16(&A2s[ob][ar][ac + j*4], &A2[(size_t)(row0+ar)*Cc + ktn + ac + j*4]);
            }
            #pragma unroll
            for (int j = 0; j < 2; ++j)
                cpa16(&Bs[ob][br][bc + j*4], &W[(size_t)(ktn+br)*Cc + col0 + bc + j*4]);
        }
        CP_COMMIT();
        CP_WAIT1();
        #pragma unroll
        for (int j = 0; j < 4; ++j) {
            float4 v  = *reinterpret_cast<float4*>(&As[buf][ar][ac + j*4]);
            float4 v2 = *reinterpret_cast<float4*>(&A2s[buf][ar][ac + j*4]);
            v.x = f2tff(v.x + v2.x); v.y = f2tff(v.y + v2.y);
            v.z = f2tff(v.z + v2.z); v.w = f2tff(v.w + v2.w);
            *reinterpret_cast<float4*>(&As[buf][ar][ac + j*4]) = v;
        }
        #pragma unroll
        for (int j = 0; j < 2; ++j) cvt_inplace4(&Bs[buf][br][bc + j*4]);
        __syncthreads();

        #pragma unroll
        for (int kc = 0; kc < 4; ++kc) {
            unsigned a[2][4];
            #pragma unroll
            for (int i = 0; i < 2; ++i) {
                int rbase = wm*32 + i*16;
                a[i][0] = __float_as_uint(As[buf][rbase+g  ][kc*8+t  ]);
                a[i][1] = __float_as_uint(As[buf][rbase+g+8][kc*8+t  ]);
                a[i][2] = __float_as_uint(As[buf][rbase+g  ][kc*8+t+4]);
                a[i][3] = __float_as_uint(As[buf][rbase+g+8][kc*8+t+4]);
            }
            #pragma unroll
            for (int j = 0; j < 4; ++j) {
                unsigned b0 = __float_as_uint(Bs[buf][kc*8+t  ][wn*32 + j*8 + g]);
                unsigned b1 = __float_as_uint(Bs[buf][kc*8+t+4][wn*32 + j*8 + g]);
                #pragma unroll
                for (int i = 0; i < 2; ++i)
                    mma8(c[i][j], a[i][0], a[i][1], a[i][2], a[i][3], b0, b1);
            }
        }
        __syncthreads();
    }

    #pragma unroll
    for (int j = 0; j < 4; ++j) {
        int cb = col0 + wn*32 + j*8 + 2*t;
        float2 bi = *reinterpret_cast<const float2*>(&bias[cb]);
        #pragma unroll
        for (int i = 0; i < 2; ++i) {
            int r0 = row0 + wm*32 + i*16 + g;
            int r1 = r0 + 8;
            *reinterpret_cast<float2*>(&out[(size_t)r0*Cc + cb]) =
                make_float2(c[i][j].x + bi.x, c[i][j].y + bi.y);
            *reinterpret_cast<float2*>(&out[(size_t)r1*Cc + cb]) =
                make_float2(c[i][j].z + bi.x, c[i][j].w + bi.y);
        }
    }
}

// ---------------------------------------------------------------------------
// Depthwise 5x5 conv (LEPE): float4/thread, branchless interior fast path.
// ---------------------------------------------------------------------------
__global__ __launch_bounds__(256) void lepe_kernel(
    const float* __restrict__ wdw, const float* __restrict__ bdw)
{
    int tid = threadIdx.x;
    int c4 = (tid & 63) * 4;
    int l = blockIdx.x * 4 + (tid >> 6);
    int b = blockIdx.y;
    int h = l / Ww;
    int w = l - h*Ww;

    float4 acc = *reinterpret_cast<const float4*>(&bdw[c4]);
    const float* vb = g_v + (size_t)b*Ll*Cc;

    if (h >= 2 && h <= Hh-3 && w >= 2 && w <= Ww-3) {
        #pragma unroll
        for (int kh = 0; kh < 5; ++kh) {
            #pragma unroll
            for (int kw = 0; kw < 5; ++kw) {
                float4 vv = *reinterpret_cast<const float4*>(
                    &vb[((size_t)(h+kh-2)*Ww + (w+kw-2))*Cc + c4]);
                float4 wt = *reinterpret_cast<const float4*>(&wdw[(kh*5+kw)*Cc + c4]);
                acc.x = fmaf(vv.x, wt.x, acc.x);
                acc.y = fmaf(vv.y, wt.y, acc.y);
                acc.z = fmaf(vv.z, wt.z, acc.z);
                acc.w = fmaf(vv.w, wt.w, acc.w);
            }
        }
    } else {
        #pragma unroll
        for (int kh = 0; kh < 5; ++kh) {
            int hh = h + kh - 2;
            if ((unsigned)hh >= (unsigned)Hh) continue;
            #pragma unroll
            for (int kw = 0; kw < 5; ++kw) {
                int ww2 = w + kw - 2;
                if ((unsigned)ww2 >= (unsigned)Ww) continue;
                float4 vv = *reinterpret_cast<const float4*>(
                    &vb[((size_t)hh*Ww + ww2)*Cc + c4]);
                float4 wt = *reinterpret_cast<const float4*>(&wdw[(kh*5+kw)*Cc + c4]);
                acc.x = fmaf(vv.x, wt.x, acc.x);
                acc.y = fmaf(vv.y, wt.y, acc.y);
                acc.z = fmaf(vv.z, wt.z, acc.z);
                acc.w = fmaf(vv.w, wt.w, acc.w);
            }
        }
    }
    *reinterpret_cast<float4*>(&g_lepe[((size_t)b*Ll + l)*Cc + c4]) = acc;
}

// ---------------------------------------------------------------------------
// Flash attention (R6 config — measured best): 256 threads = 8 warps,
// 16 Q-rows/warp, KV tiles of 64, cp.async K/V double-buffer + mask tile.
// dynamic smem: Ks[2][64][36] | Vs[2][64][40] | Ps[8][16][68] | Ms[128][68]
// ---------------------------------------------------------------------------
#define KS_OFF 0
#define VS_OFF (2*64*36)
#define PS_OFF (VS_OFF + 2*64*40)
#define MS_OFF (PS_OFF + 8*16*68)
#define ATT_SMEM (MS_OFF + 128*68)

__global__ __launch_bounds__(256, 2) void attn_tc_kernel(const float* __restrict__ mask)
{
    extern __shared__ float sm[];
    float (*Ks)[64][36] = reinterpret_cast<float(*)[64][36]>(sm + KS_OFF);
    float (*Vs)[64][40] = reinterpret_cast<float(*)[64][40]>(sm + VS_OFF);
    float (*Ps)[16][68] = reinterpret_cast<float(*)[16][68]>(sm + PS_OFF);
    float (*Ms)[68]     = reinterpret_cast<float(*)[68]>(sm + MS_OFF);

    int tid  = threadIdx.x;
    int warp = tid >> 5, lane = tid & 31;
    int g = lane >> 2, t = lane & 3;
    int n = blockIdx.y >> 1, b = blockIdx.y & 1;
    int l0 = blockIdx.x * 128;
    int qrow = l0 + warp*16;

    const float* qb = g_q + ((size_t)(b*Ll + qrow))*Cc + n*HDd;
    const float* kb = g_k + ((size_t)b*Ll)*Cc + n*HDd;
    const float* vb = g_v + ((size_t)b*Ll)*Cc + n*HDd;
    const float* mbb = mask + ((size_t)n*Ll + l0)*Ll;

    unsigned qa[4][4];
    #pragma unroll
    for (int kc = 0; kc < 4; ++kc) {
        qa[kc][0] = f2tf(qb[(size_t)g*Cc     + kc*8 + t]);
        qa[kc][1] = f2tf(qb[(size_t)(g+8)*Cc + kc*8 + t]);
        qa[kc][2] = f2tf(qb[(size_t)g*Cc     + kc*8 + t + 4]);
        qa[kc][3] = f2tf(qb[(size_t)(g+8)*Cc + kc*8 + t + 4]);
    }

    int sr = tid >> 3;            // 0..31
    int sc = (tid & 7) * 4;

    cpa16(&Ks[0][sr   ][sc], &kb[(size_t)(sr   )*Cc + sc]);
    cpa16(&Ks[0][sr+32][sc], &kb[(size_t)(sr+32)*Cc + sc]);
    cpa16(&Vs[0][sr   ][sc], &vb[(size_t)(sr   )*Cc + sc]);
    cpa16(&Vs[0][sr+32][sc], &vb[(size_t)(sr+32)*Cc + sc]);
    CP_COMMIT();

    float mA = -1e30f, mB = -1e30f, lA = 0.f, lB = 0.f;
    float4 o[4] = {};

    for (int tile = 0; tile < Ll/64; ++tile) {
        int buf = tile & 1;
        int m0 = tile * 64;

        #pragma unroll
        for (int kk = 0; kk < 8; ++kk) {
            int oidx = tid + kk*256;
            int mr = oidx >> 4, seg = (oidx & 15) * 4;
            cpa16(&Ms[mr][seg], &mbb[(size_t)mr*Ll + m0 + seg]);
        }
        CP_COMMIT();

        if (m0 + 64 < Ll) {
            int nb0 = m0 + 64, ob = buf ^ 1;
            cpa16(&Ks[ob][sr   ][sc], &kb[(size_t)(nb0+sr   )*Cc + sc]);
            cpa16(&Ks[ob][sr+32][sc], &kb[(size_t)(nb0+sr+32)*Cc + sc]);
            cpa16(&Vs[ob][sr   ][sc], &vb[(size_t)(nb0+sr   )*Cc + sc]);
            cpa16(&Vs[ob][sr+32][sc], &vb[(size_t)(nb0+sr+32)*Cc + sc]);
        }
        CP_COMMIT();

        CP_WAIT2();
        cvt_inplace4(&Ks[buf][sr   ][sc]);
        cvt_inplace4(&Ks[buf][sr+32][sc]);
        cvt_inplace4(&Vs[buf][sr   ][sc]);
        cvt_inplace4(&Vs[buf][sr+32][sc]);
        __syncthreads();

        float4 s[8];
        #pragma unroll
        for (int nb = 0; nb < 8; ++nb) {
            s[nb] = make_float4(0.f, 0.f, 0.f, 0.f);
            #pragma unroll
            for (int kc = 0; kc < 4; ++kc) {
                unsigned b0 = __float_as_uint(Ks[buf][nb*8+g][kc*8+t]);
                unsigned b1 = __float_as_uint(Ks[buf][nb*8+g][kc*8+t+4]);
                mma8(s[nb], qa[kc][0], qa[kc][1], qa[kc][2], qa[kc][3], b0, b1);
            }
        }

        CP_WAIT1();
        __syncthreads();

        int mrA = warp*16 + g, mrB = mrA + 8;
        float mxA = -1e30f, mxB = -1e30f;
        #pragma unroll
        for (int nb = 0; nb < 8; ++nb) {
            float2 ma = *reinterpret_cast<const float2*>(&Ms[mrA][nb*8 + 2*t]);
            float2 mc = *reinterpret_cast<const float2*>(&Ms[mrB][nb*8 + 2*t]);
            s[nb].x += ma.x; s[nb].y += ma.y;
            s[nb].z += mc.x; s[nb].w += mc.y;
            mxA = fmaxf(mxA, fmaxf(s[nb].x, s[nb].y));
            mxB = fmaxf(mxB, fmaxf(s[nb].z, s[nb].w));
        }
        mxA = fmaxf(mxA, __shfl_xor_sync(0xffffffffu, mxA, 1));
        mxA = fmaxf(mxA, __shfl_xor_sync(0xffffffffu, mxA, 2));
        mxB = fmaxf(mxB, __shfl_xor_sync(0xffffffffu, mxB, 1));
        mxB = fmaxf(mxB, __shfl_xor_sync(0xffffffffu, mxB, 2));

        float mAn = fmaxf(mA, mxA), mBn = fmaxf(mB, mxB);
        float scA = __expf(mA - mAn), scB = __expf(mB - mBn);
        mA = mAn; mB = mBn;

        float sA = 0.f, sB = 0.f;
        #pragma unroll
        for (int nb = 0; nb < 8; ++nb) {
            float p0 = __expf(s[nb].x - mA);
            float p1 = __expf(s[nb].y - mA);
            float p2 = __expf(s[nb].z - mB);
            float p3 = __expf(s[nb].w - mB);
            sA += p0 + p1; sB += p2 + p3;
            Ps[warp][g  ][nb*8 + 2*t    ] = __uint_as_float(f2tf(p0));
            Ps[warp][g  ][nb*8 + 2*t + 1] = __uint_as_float(f2tf(p1));
            Ps[warp][g+8][nb*8 + 2*t    ] = __uint_as_float(f2tf(p2));
            Ps[warp][g+8][nb*8 + 2*t + 1] = __uint_as_float(f2tf(p3));
        }
        sA += __shfl_xor_sync(0xffffffffu, sA, 1);
        sA += __shfl_xor_sync(0xffffffffu, sA, 2);
        sB += __shfl_xor_sync(0xffffffffu, sB, 1);
        sB += __shfl_xor_sync(0xffffffffu, sB, 2);
        lA = lA*scA + sA;
        lB = lB*scB + sB;

        #pragma unroll
        for (int nv = 0; nv < 4; ++nv) {
            o[nv].x *= scA; o[nv].y *= scA;
            o[nv].z *= scB; o[nv].w *= scB;
        }
        __syncwarp();

        #pragma unroll
        for (int kc = 0; kc < 8; ++kc) {
            unsigned a0 = __float_as_uint(Ps[warp][g  ][kc*8 + t    ]);
            unsigned a1 = __float_as_uint(Ps[warp][g+8][kc*8 + t    ]);
            unsigned a2 = __float_as_uint(Ps[warp][g  ][kc*8 + t + 4]);
            unsigned a3 = __float_as_uint(Ps[warp][g+8][kc*8 + t + 4]);
            #pragma unroll
            for (int nv = 0; nv < 4; ++nv) {
                unsigned b0 = __float_as_uint(Vs[buf][kc*8 + t    ][nv*8 + g]);
                unsigned b1 = __float_as_uint(Vs[buf][kc*8 + t + 4][nv*8 + g]);
                mma8(o[nv], a0, a1, a2, a3, b0, b1);
            }
        }
        __syncthreads();
    }

    float invA = 1.f / lA, invB = 1.f / lB;
    float* ob = g_attn + ((size_t)(b*Ll + qrow))*Cc + n*HDd;
    #pragma unroll
    for (int nv = 0; nv < 4; ++nv) {
        float2 wA = make_float2(o[nv].x*invA, o[nv].y*invA);
        float2 wB = make_float2(o[nv].z*invB, o[nv].w*invB);
        *reinterpret_cast<float2*>(&ob[(size_t)g*Cc     + nv*8 + 2*t]) = wA;
        *reinterpret_cast<float2*>(&ob[(size_t)(g+8)*Cc + nv*8 + 2*t]) = wB;
    }
}

// ---------------------------------------------------------------------------
extern "C" void kernel_launch(void* const* d_in, const int* in_sizes, int n_in,
                              void* d_out, int out_size)
{
    const float* x    = (const float*)d_in[0];
    const float* sinp = (const float*)d_in[1];
    const float* cosp = (const float*)d_in[2];
    const float* mask = (const float*)d_in[3];
    const float* wq   = (const float*)d_in[4];
    const float* bq   = (const float*)d_in[5];
    const float* wk   = (const float*)d_in[6];
    const float* bk   = (const float*)d_in[7];
    const float* wv   = (const float*)d_in[8];
    const float* bv   = (const float*)d_in[9];
    const float* wdw  = (const float*)d_in[10];
    const float* bdw  = (const float*)d_in[11];
    const float* wo   = (const float*)d_in[12];
    const float* bo   = (const float*)d_in[13];

    float *pa, *pl;
    cudaGetSymbolAddress((void**)&pa, g_attn);
    cudaGetSymbolAddress((void**)&pl, g_lepe);

    cudaFuncSetAttribute(attn_tc_kernel, cudaFuncAttributeMaxDynamicSharedMemorySize,
                         ATT_SMEM * (int)sizeof(float));
    cudaFuncSetAttribute(qkv_tc_kernel, cudaFuncAttributeMaxDynamicSharedMemorySize,
                         QKV_SMEM * (int)sizeof(float));
    cudaFuncSetAttribute(gemm_tc_kernel, cudaFuncAttributeMaxDynamicSharedMemorySize,
                         OP_SMEM * (int)sizeof(float));

    dim3 gg(Rr/128, Cc/64);   // 36 x 4 = 144 blocks, one wave
    qkv_tc_kernel<<<gg, 256, QKV_SMEM*sizeof(float)>>>(x, wq, bq, wk, bk, wv, bv, sinp, cosp);

    lepe_kernel<<<dim3(Ll/4, Bb), 256>>>(wdw, bdw);

    attn_tc_kernel<<<dim3(Ll/128, Bb*NHh), 256, ATT_SMEM*sizeof(float)>>>(mask);

    gemm_tc_kernel<<<gg, 256, OP_SMEM*sizeof(float)>>>(pa, pl, wo, bo, (float*)d_out);
}